// round 1
// baseline (speedup 1.0000x reference)
#include <cuda_runtime.h>

// SSIM loss, fused single pass:
//   4 separable 11-tap convs (x, y, x*y, x^2+y^2), horizontal then vertical,
//   per-pixel SSIM, global mean via block reduction + double atomic.
// Tile: 32 wide x 32 tall outputs, halo 5 -> 42x42 input region. 256 threads.

#define TW 32
#define TH 32
#define RW 42          // TW + 10
#define RH 42          // TH + 10
#define SXP 45         // padded row stride for input tiles (bank-conflict-free)
#define HP  33         // padded row stride for intermediate tiles
#define NTHREADS 256
#define NPIX (16*3*512*512)

// Gaussian(sigma=1.5) 11-tap, normalized (matches jax reference to ~1e-7)
__device__ constexpr float Wg[11] = {
    0.00102838f, 0.00759875f, 0.03600077f, 0.10936070f, 0.21300553f,
    0.26601172f,
    0.21300553f, 0.10936070f, 0.03600077f, 0.00759875f, 0.00102838f};

__device__ double g_acc;

__global__ void ssim_zero() { g_acc = 0.0; }

__global__ void __launch_bounds__(NTHREADS)
ssim_main(const float* __restrict__ pred, const float* __restrict__ targ) {
    __shared__ float sx[RH][SXP];
    __shared__ float sy[RH][SXP];
    __shared__ float hh[4][RH][HP];
    __shared__ float red[8];

    const int tid = threadIdx.x;
    const int plane = blockIdx.z;
    const int gx0 = blockIdx.x * TW - 5;
    const int gy0 = blockIdx.y * TH - 5;
    const float* __restrict__ px = pred + (size_t)plane * (512 * 512);
    const float* __restrict__ py = targ + (size_t)plane * (512 * 512);

    // ---- load 42x42 halo region (zero-padded at image borders) ----
    for (int i = tid; i < RH * RW; i += NTHREADS) {
        int r = i / RW;
        int c = i - r * RW;
        int gy = gy0 + r, gx = gx0 + c;
        float vx = 0.f, vy = 0.f;
        if ((unsigned)gy < 512u && (unsigned)gx < 512u) {
            int idx = gy * 512 + gx;
            vx = px[idx];
            vy = py[idx];
        }
        sx[r][c] = vx;
        sy[r][c] = vy;
    }
    __syncthreads();

    // ---- horizontal pass: 42 rows x 4 segments of 8 outputs ----
    // per segment: 18 loads/map-input, 8 outputs x 4 maps x 11 imm-FMA taps
    for (int t = tid; t < RH * 4; t += NTHREADS) {
        const int row = t >> 2;
        const int c0 = (t & 3) * 8;
        float a[18], b[18];
#pragma unroll
        for (int k = 0; k < 18; k++) {
            a[k] = sx[row][c0 + k];
            b[k] = sy[row][c0 + k];
        }
        float ax[8], ay[8], ap[8], as_[8];
#pragma unroll
        for (int j = 0; j < 8; j++) ax[j] = ay[j] = ap[j] = as_[j] = 0.f;

#pragma unroll
        for (int k = 0; k < 11; k++) {
#pragma unroll
            for (int j = 0; j < 8; j++) {
                ax[j] += Wg[k] * a[j + k];   // FFMA-imm
                ay[j] += Wg[k] * b[j + k];
            }
        }
        float pb[18], sb[18];
#pragma unroll
        for (int k = 0; k < 18; k++) {
            pb[k] = a[k] * b[k];
            sb[k] = fmaf(a[k], a[k], b[k] * b[k]);
        }
#pragma unroll
        for (int k = 0; k < 11; k++) {
#pragma unroll
            for (int j = 0; j < 8; j++) {
                ap[j]  += Wg[k] * pb[j + k];
                as_[j] += Wg[k] * sb[j + k];
            }
        }
#pragma unroll
        for (int j = 0; j < 8; j++) {
            hh[0][row][c0 + j] = ax[j];
            hh[1][row][c0 + j] = ay[j];
            hh[2][row][c0 + j] = ap[j];
            hh[3][row][c0 + j] = as_[j];
        }
    }
    __syncthreads();

    // ---- vertical pass: each thread owns column tx, 4 consecutive rows ----
    const int tx = tid & 31;
    const int g = tid >> 5;          // 0..7 -> output rows g*4 .. g*4+3
    float acc[4][4];
#pragma unroll
    for (int m = 0; m < 4; m++)
#pragma unroll
        for (int j = 0; j < 4; j++) acc[m][j] = 0.f;

#pragma unroll
    for (int m = 0; m < 4; m++) {
        float v[14];
#pragma unroll
        for (int k = 0; k < 14; k++) v[k] = hh[m][g * 4 + k][tx];
#pragma unroll
        for (int k = 0; k < 11; k++)
#pragma unroll
            for (int j = 0; j < 4; j++)
                acc[m][j] += Wg[k] * v[j + k];   // FFMA-imm
    }

    // ---- SSIM + thread-local sum ----
    const float C1 = 1e-4f, C2 = 9e-4f;
    float local = 0.f;
#pragma unroll
    for (int j = 0; j < 4; j++) {
        float mx = acc[0][j], my = acc[1][j];
        float ep = acc[2][j], es = acc[3][j];
        float muxy = mx * my;
        float mu2  = fmaf(mx, mx, my * my);
        float sxy  = ep - muxy;
        float ssum = es - mu2;
        float num = (2.f * muxy + C1) * (2.f * sxy + C2);
        float den = (mu2 + C1) * (ssum + C2);
        local += __fdividef(num, den);
    }

    // ---- block reduce -> one double atomic per block ----
#pragma unroll
    for (int o = 16; o > 0; o >>= 1)
        local += __shfl_down_sync(0xffffffffu, local, o);
    if (tx == 0) red[g] = local;
    __syncthreads();
    if (tid == 0) {
        float s = 0.f;
#pragma unroll
        for (int i = 0; i < 8; i++) s += red[i];
        atomicAdd(&g_acc, (double)s);
    }
}

__global__ void ssim_fin(float* out) {
    out[0] = 1.0f - (float)(g_acc * (1.0 / (double)NPIX));
}

extern "C" void kernel_launch(void* const* d_in, const int* in_sizes, int n_in,
                              void* d_out, int out_size) {
    const float* pred = (const float*)d_in[0];
    const float* targ = (const float*)d_in[1];
    float* out = (float*)d_out;

    ssim_zero<<<1, 1>>>();
    dim3 grid(512 / TW, 512 / TH, 48);
    ssim_main<<<grid, NTHREADS>>>(pred, targ);
    ssim_fin<<<1, 1>>>(out);
}